// round 4
// baseline (speedup 1.0000x reference)
#include <cuda_runtime.h>

// GraphConvolution: out = segment_sum(edge_val * (x@W)[edge_col] by edge_row) + b
// N=50000, E=800000, D_IN=D_OUT=96
// Strategy: dense GEMM -> on-the-fly CSR bucketing -> atomic-free SpMM (+bias).

#define DIN  96
#define DOUT 96
#define MAXN 50000
#define MAXE 800000

__device__ float g_support[(size_t)MAXN * DOUT];
__device__ int   g_cnt[MAXN];        // degree per row
__device__ int   g_rowstart[MAXN];   // segment start per row
__device__ int   g_fillpos[MAXN];    // running fill cursor (destroyed in pass 4)
__device__ int2  g_edges[MAXE];      // (col, val-bits) grouped by row
__device__ int   g_total;            // segment allocator

// ---------------------------------------------------------------------------
// Pass 1: zero counters + allocator.
__global__ void zero_kernel(int N) {
    int i = blockIdx.x * blockDim.x + threadIdx.x;
    if (i < N) g_cnt[i] = 0;
    if (i == 0) g_total = 0;
}

// Pass 2: histogram of edge_row.
__global__ void hist_kernel(const int* __restrict__ er, int E) {
    int e = blockIdx.x * blockDim.x + threadIdx.x;
    if (e < E) atomicAdd(&g_cnt[__ldg(er + e)], 1);
}

// Pass 3: allocate contiguous segment per row (warp-aggregated single atomic).
__global__ void alloc_kernel(int N) {
    int i = blockIdx.x * blockDim.x + threadIdx.x;
    int lane = threadIdx.x & 31;
    int c = (i < N) ? g_cnt[i] : 0;
    int v = c;
#pragma unroll
    for (int d = 1; d < 32; d <<= 1) {
        int t = __shfl_up_sync(0xffffffffu, v, d);
        if (lane >= d) v += t;
    }
    int wtot = __shfl_sync(0xffffffffu, v, 31);
    int base = 0;
    if (lane == 31) base = atomicAdd(&g_total, wtot);
    base = __shfl_sync(0xffffffffu, base, 31);
    int start = base + v - c;           // exclusive within warp
    if (i < N) { g_rowstart[i] = start; g_fillpos[i] = start; }
}

// Pass 4: bucket (col, val) pairs into per-row segments.
__global__ void bucket_kernel(const int*   __restrict__ er,
                              const int*   __restrict__ ec,
                              const float* __restrict__ ev, int E) {
    int e = blockIdx.x * blockDim.x + threadIdx.x;
    if (e < E) {
        int r = __ldg(er + e);
        int p = atomicAdd(&g_fillpos[r], 1);
        g_edges[p] = make_int2(__ldg(ec + e), __float_as_int(__ldg(ev + e)));
    }
}

// ---------------------------------------------------------------------------
// support = x @ W.   W staged in shared; each thread: 4 rows x 4 cols.
__global__ void __launch_bounds__(384)
gemm_kernel(const float* __restrict__ x,
            const float* __restrict__ w,
            float* __restrict__ sup, int N) {
    __shared__ float4 Ws[DIN][DOUT / 4];

    int tid = threadIdx.x;
    const float4* w4 = (const float4*)w;
#pragma unroll
    for (int i = tid; i < DIN * DOUT / 4; i += 384)
        Ws[i / (DOUT / 4)][i % (DOUT / 4)] = w4[i];
    __syncthreads();

    int c4 = tid % 24;
    int r0 = blockIdx.x * 64 + (tid / 24) * 4;

    const float4* xr[4];
    bool valid[4];
#pragma unroll
    for (int j = 0; j < 4; j++) {
        int row  = r0 + j;
        valid[j] = (row < N);
        int rowc = valid[j] ? row : (N - 1);
        xr[j] = (const float4*)(x + (size_t)rowc * DIN);
    }

    float4 acc[4];
#pragma unroll
    for (int j = 0; j < 4; j++) acc[j] = make_float4(0.f, 0.f, 0.f, 0.f);

#pragma unroll 4
    for (int kk = 0; kk < DIN / 4; kk++) {
        float4 xv[4];
#pragma unroll
        for (int j = 0; j < 4; j++) xv[j] = __ldg(xr[j] + kk);
#pragma unroll
        for (int t = 0; t < 4; t++) {
            float4 wv = Ws[kk * 4 + t][c4];
#pragma unroll
            for (int j = 0; j < 4; j++) {
                float xs = (t == 0) ? xv[j].x : (t == 1) ? xv[j].y
                                              : (t == 2) ? xv[j].z : xv[j].w;
                acc[j].x += xs * wv.x;
                acc[j].y += xs * wv.y;
                acc[j].z += xs * wv.z;
                acc[j].w += xs * wv.w;
            }
        }
    }

#pragma unroll
    for (int j = 0; j < 4; j++)
        if (valid[j])
            ((float4*)(sup + (size_t)(r0 + j) * DOUT))[c4] = acc[j];
}

// ---------------------------------------------------------------------------
// Pass 5: SpMM + bias. One 24-thread group per row; register accumulation;
// single float4 store per (row, c4). No atomics.
__global__ void __launch_bounds__(384)
spmm_kernel(const float* __restrict__ sup,
            const float* __restrict__ b,
            float* __restrict__ out, int N) {
    int row = blockIdx.x * 16 + threadIdx.x / 24;
    int c4  = threadIdx.x % 24;
    if (row >= N) return;

    int s   = g_rowstart[row];
    int len = g_cnt[row];

    float4 acc = make_float4(0.f, 0.f, 0.f, 0.f);
    int j = 0;
    // 2-way unrolled for MLP
    for (; j + 2 <= len; j += 2) {
        int2 cv0 = g_edges[s + j];
        int2 cv1 = g_edges[s + j + 1];
        float4 s0 = __ldg((const float4*)(sup + (size_t)cv0.x * DOUT) + c4);
        float4 s1 = __ldg((const float4*)(sup + (size_t)cv1.x * DOUT) + c4);
        float v0 = __int_as_float(cv0.y);
        float v1 = __int_as_float(cv1.y);
        acc.x += v0 * s0.x; acc.y += v0 * s0.y;
        acc.z += v0 * s0.z; acc.w += v0 * s0.w;
        acc.x += v1 * s1.x; acc.y += v1 * s1.y;
        acc.z += v1 * s1.z; acc.w += v1 * s1.w;
    }
    if (j < len) {
        int2 cv = g_edges[s + j];
        float4 sv = __ldg((const float4*)(sup + (size_t)cv.x * DOUT) + c4);
        float v = __int_as_float(cv.y);
        acc.x += v * sv.x; acc.y += v * sv.y;
        acc.z += v * sv.z; acc.w += v * sv.w;
    }

    float4 bb = __ldg((const float4*)b + c4);
    acc.x += bb.x; acc.y += bb.y; acc.z += bb.z; acc.w += bb.w;
    ((float4*)(out + (size_t)row * DOUT))[c4] = acc;
}

// ---------------------------------------------------------------------------
extern "C" void kernel_launch(void* const* d_in, const int* in_sizes, int n_in,
                              void* d_out, int out_size) {
    const float* x      = (const float*)d_in[0];
    const int*   e_row  = (const int*)  d_in[1];
    const int*   e_col  = (const int*)  d_in[2];
    const float* e_val  = (const float*)d_in[3];
    const float* weight = (const float*)d_in[4];
    const float* bias   = (const float*)d_in[5];
    float*       out    = (float*)d_out;

    int N = in_sizes[0] / DIN;
    int E = in_sizes[1];

    float* sup;
    cudaGetSymbolAddress((void**)&sup, g_support);

    // CSR build
    zero_kernel  <<<(N + 255) / 256, 256>>>(N);
    hist_kernel  <<<(E + 255) / 256, 256>>>(e_row, E);
    alloc_kernel <<<(N + 255) / 256, 256>>>(N);
    bucket_kernel<<<(E + 255) / 256, 256>>>(e_row, e_col, e_val, E);

    // Dense GEMM
    gemm_kernel<<<(N + 63) / 64, 384>>>(x, weight, sup, N);

    // Atomic-free SpMM + bias
    spmm_kernel<<<(N + 15) / 16, 384>>>(sup, bias, out, N);
}